// round 11
// baseline (speedup 1.0000x reference)
#include <cuda_runtime.h>
#include <cuda_bf16.h>

#define MAXN 50000
#define MAXE 800000
#define NGRAPH 128

typedef unsigned long long u64;

// Scratch (device globals; zero-initialized at module load).
// Invariants at entry of every launch: g_EA, g_deg, g_sc, g_bar are zero.
// Restored each call inside the kernel (deg in phase3, EA+sc in phase8,
// g_bar by the terminal arrive).
__device__ float          g_h[MAXN * 64];
__device__ __nv_bfloat16  g_t0[MAXN * 64];
__device__ __nv_bfloat16  g_t1[MAXN * 64];
__device__ float          g_pre[MAXN * 64];
__device__ float          g_EA[MAXN * 12];
__device__ int            g_deg[MAXN];
__device__ int            g_off[MAXN + 1];
__device__ int            g_cur[MAXN];
__device__ int            g_csr[MAXE];
__device__ int            g_part[2048];
__device__ float          g_sc[2 * NGRAPH];
__device__ unsigned int   g_bar;

__device__ __forceinline__ float lrelu(float a) { return a > 0.0f ? a : 0.01f * a; }

__device__ __forceinline__ void fma2(u64& d, u64 a, u64 b) {
    asm("fma.rn.f32x2 %0, %1, %2, %0;" : "+l"(d) : "l"(a), "l"(b));
}
__device__ __forceinline__ u64 pack2(float a) {
    u64 r; unsigned int ai = __float_as_uint(a);
    asm("mov.b64 %0, {%1, %1};" : "=l"(r) : "r"(ai));
    return r;
}
__device__ __forceinline__ unsigned int bf2_from_u64(u64 p) {
    unsigned int lo, hi, r;
    asm("mov.b64 {%0, %1}, %2;" : "=r"(lo), "=r"(hi) : "l"(p));
    asm("cvt.rn.bf16x2.f32 %0, %1, %2;" : "=r"(r)
        : "f"(__uint_as_float(hi)), "f"(__uint_as_float(lo)));
    return r;
}
__device__ __forceinline__ void red_add_v4(float* addr, float4 v) {
    asm volatile("red.global.add.v4.f32 [%0], {%1,%2,%3,%4};"
                 :: "l"(addr), "f"(v.x), "f"(v.y), "f"(v.z), "f"(v.w) : "memory");
}

// grid-wide barrier: counter + acquire-load spin (all blocks resident)
__device__ __forceinline__ void gsync(int epoch, unsigned int grid) {
    __syncthreads();
    if (threadIdx.x == 0) {
        __threadfence();
        atomicAdd(&g_bar, 1u);
        unsigned int want = (unsigned int)epoch * grid;
        unsigned int v;
        do {
            asm volatile("ld.acquire.gpu.u32 %0, [%1];" : "=r"(v) : "l"(&g_bar));
            if (v < want) __nanosleep(32);
        } while (v < want);
        __threadfence();
    }
    __syncthreads();
}

// smem layout (floats)
#define OFF_X   0
#define OFF_W   4352
#define OFF_B   12544
#define OFF_WE  12608
#define OFF_WIN 13376
#define OFF_BIN 14144
#define SMEM_FLOATS 14208

// ---------------------------------------------------------------------------
// GEMM for one 64-node tile (weights already staged in sm).
//   FIRST: X = lrelu([state|action]@W_in + b_in) in-loader; else X = h.
//   t = X @ W_nbr (bf16x2);  pre = X @ W_self + bias.
// ---------------------------------------------------------------------------
template<bool FIRST>
__device__ __forceinline__ void gemm_tile(
    float* sm, int base, int N,
    const float* __restrict__ state, const float* __restrict__ action,
    const float* __restrict__ h,
    __nv_bfloat16* __restrict__ t, float* __restrict__ pre) {
    int tid = threadIdx.x;

    if (FIRST) {
        int node = tid & 63, q = tid >> 6;
        int gn = base + node;
        float xin[12];
#pragma unroll
        for (int k = 0; k < 12; k++) xin[k] = 0.0f;
        if (gn < N) {
#pragma unroll
            for (int k = 0; k < 8; k++) xin[k] = state[gn * 8 + k];
#pragma unroll
            for (int k = 0; k < 4; k++) xin[8 + k] = action[gn * 4 + k];
        }
        int c0 = q * 16;
#pragma unroll 4
        for (int c = c0; c < c0 + 16; c++) {
            float a = sm[OFF_BIN + c];
#pragma unroll
            for (int k = 0; k < 12; k++) a += xin[k] * sm[OFF_WIN + k * 64 + c];
            sm[OFF_X + node * 68 + c] = lrelu(a);
        }
    } else {
        for (int j = tid; j < 1024; j += 256) {
            int node = j >> 4, kq = j & 15;
            int gn = base + node;
            float4 v = make_float4(0.f, 0.f, 0.f, 0.f);
            if (gn < N) v = ((const float4*)h)[gn * 16 + kq];
            *(float4*)&sm[OFF_X + node * 68 + kq * 4] = v;
        }
    }
    __syncthreads();

    int ty = tid >> 4;
    int tx = tid & 15;
    bool isPre = tx >= 8;
    int cb = (tx & 7) * 8;

    u64 acc[4][4];
    if (isPre) {
        const u64* b2 = (const u64*)&sm[OFF_B + cb];
#pragma unroll
        for (int n = 0; n < 4; n++) {
            acc[n][0] = b2[0]; acc[n][1] = b2[1];
            acc[n][2] = b2[2]; acc[n][3] = b2[3];
        }
    } else {
#pragma unroll
        for (int n = 0; n < 4; n++)
#pragma unroll
            for (int q = 0; q < 4; q++) acc[n][q] = 0ull;
    }

    const float* xrow  = &sm[OFF_X + ty * 4 * 68];
    const float* wbase = &sm[OFF_W + (isPre ? 64 : 0) + cb];

#pragma unroll 4
    for (int k = 0; k < 64; k++) {
        const ulonglong2* w2 = (const ulonglong2*)(wbase + k * 128);
        ulonglong2 wa = w2[0], wb = w2[1];
#pragma unroll
        for (int n = 0; n < 4; n++) {
            u64 a = pack2(xrow[n * 68 + k]);
            fma2(acc[n][0], a, wa.x); fma2(acc[n][1], a, wa.y);
            fma2(acc[n][2], a, wb.x); fma2(acc[n][3], a, wb.y);
        }
    }

    if (isPre) {
#pragma unroll
        for (int n = 0; n < 4; n++) {
            int gn = base + ty * 4 + n;
            if (gn < N) {
                ulonglong2* o = (ulonglong2*)(pre + gn * 64 + cb);
                o[0] = make_ulonglong2(acc[n][0], acc[n][1]);
                o[1] = make_ulonglong2(acc[n][2], acc[n][3]);
            }
        }
    } else {
#pragma unroll
        for (int n = 0; n < 4; n++) {
            int gn = base + ty * 4 + n;
            if (gn < N) {
                uint4 o;
                o.x = bf2_from_u64(acc[n][0]);
                o.y = bf2_from_u64(acc[n][1]);
                o.z = bf2_from_u64(acc[n][2]);
                o.w = bf2_from_u64(acc[n][3]);
                *(uint4*)(t + gn * 64 + cb) = o;
            }
        }
    }
    __syncthreads();
}

// ---------------------------------------------------------------------------
// Pull for one node (warp-collective): s = pre + EA@We(smem) + sum t[src].
// Returns the lane's two accumulated channels.
// ---------------------------------------------------------------------------
__device__ __forceinline__ float2 pull_node(
    const float* sm, int node, int lane,
    const int* __restrict__ off, const int* __restrict__ csr,
    const __nv_bfloat16* __restrict__ t, const float* __restrict__ pre,
    const float* __restrict__ EA) {
    int s = off[node], e = off[node + 1];
    const __nv_bfloat162* t2 = (const __nv_bfloat162*)t;
    float2 p = ((const float2*)pre)[node * 32 + lane];
    float ax = p.x, ay = p.y;

    float eav = (lane < 12) ? EA[node * 12 + lane] : 0.0f;
    const float2* We2 = (const float2*)&sm[OFF_WE];
#pragma unroll
    for (int k = 0; k < 12; k++) {
        float a = __shfl_sync(0xffffffffu, eav, k);
        float2 w = We2[k * 32 + lane];
        ax += a * w.x; ay += a * w.y;
    }

    for (int j = s; j < e; j += 32) {
        int cnt = min(32, e - j);
        int sv = (j + lane < e) ? csr[j + lane] : 0;
        int i = 0;
#pragma unroll 1
        for (; i + 8 <= cnt; i += 8) {
            int b0 = __shfl_sync(0xffffffffu, sv, i + 0);
            int b1 = __shfl_sync(0xffffffffu, sv, i + 1);
            int b2 = __shfl_sync(0xffffffffu, sv, i + 2);
            int b3 = __shfl_sync(0xffffffffu, sv, i + 3);
            int b4 = __shfl_sync(0xffffffffu, sv, i + 4);
            int b5 = __shfl_sync(0xffffffffu, sv, i + 5);
            int b6 = __shfl_sync(0xffffffffu, sv, i + 6);
            int b7 = __shfl_sync(0xffffffffu, sv, i + 7);
            float2 v0 = __bfloat1622float2(t2[b0 * 32 + lane]);
            float2 v1 = __bfloat1622float2(t2[b1 * 32 + lane]);
            float2 v2 = __bfloat1622float2(t2[b2 * 32 + lane]);
            float2 v3 = __bfloat1622float2(t2[b3 * 32 + lane]);
            float2 v4 = __bfloat1622float2(t2[b4 * 32 + lane]);
            float2 v5 = __bfloat1622float2(t2[b5 * 32 + lane]);
            float2 v6 = __bfloat1622float2(t2[b6 * 32 + lane]);
            float2 v7 = __bfloat1622float2(t2[b7 * 32 + lane]);
            ax += ((v0.x + v1.x) + (v2.x + v3.x)) + ((v4.x + v5.x) + (v6.x + v7.x));
            ay += ((v0.y + v1.y) + (v2.y + v3.y)) + ((v4.y + v5.y) + (v6.y + v7.y));
        }
#pragma unroll 1
        for (; i < cnt; i++) {
            int b = __shfl_sync(0xffffffffu, sv, i);
            float2 v = __bfloat1622float2(t2[b * 32 + lane]);
            ax += v.x; ay += v.y;
        }
    }
    return make_float2(ax, ay);
}

// ---------------------------------------------------------------------------
// The persistent mega-kernel: all phases, grid barriers in between.
// ---------------------------------------------------------------------------
__global__ void __launch_bounds__(256, 3)
k_all(const float* __restrict__ state, const float* __restrict__ action,
      const int* __restrict__ ei, const float* __restrict__ edge_attr,
      const int* __restrict__ batch,
      const float* __restrict__ Win, const float* __restrict__ bin,
      const float* __restrict__ Wself, const float* __restrict__ Wnbr,
      const float* __restrict__ Wedge, const float* __restrict__ bconv,
      const float* __restrict__ Wout, const float* __restrict__ bout,
      float* __restrict__ out, int N, int E, int G, int grid) {
    extern __shared__ float sm[];
    __shared__ int swarp[8];
    __shared__ int sprefix, stotal;

    int tid = threadIdx.x, bid = blockIdx.x;
    int lane = tid & 31, warp = tid >> 5;
    int epoch = 0;
    int tiles = (N + 63) >> 6;

    // ===== Phase 1: gemm0 (readin fused) + edge hist/EA =====
    for (int j = tid; j < 768; j += 256) sm[OFF_WIN + j] = Win[j];
    if (tid < 64) sm[OFF_BIN + tid] = bin[tid];
    for (int j = tid; j < 2048; j += 256) {
        int k = j >> 5, c4 = j & 31;
        float4 wv = (c4 < 16) ? ((const float4*)Wnbr)[k * 16 + c4]
                              : ((const float4*)Wself)[k * 16 + (c4 - 16)];
        *(float4*)&sm[OFF_W + k * 128 + c4 * 4] = wv;
    }
    if (tid < 64) sm[OFF_B + tid] = bconv[tid];
    __syncthreads();
    for (int tile = bid; tile < tiles; tile += grid)
        gemm_tile<true>(sm, tile * 64, N, state, action, nullptr, g_t0, g_pre);

    for (int e = bid * 256 + tid; e < E; e += grid * 256) {
        int dst = ei[E + e];
        atomicAdd(&g_deg[dst], 1);
        const float4* a4 = (const float4*)(edge_attr + (size_t)e * 12);
        float4 v0 = a4[0], v1 = a4[1], v2 = a4[2];
        float* base = g_EA + dst * 12;
        red_add_v4(base, v0);
        red_add_v4(base + 4, v1);
        red_add_v4(base + 8, v2);
    }
    gsync(++epoch, grid);

    // ===== Phase 2: per-block degree partial sums =====
    int chunk = (N + grid - 1) / grid;
    int c0 = bid * chunk, c1 = min(c0 + chunk, N);
    {
        int s = 0;
        for (int i = c0 + tid; i < c1; i += 256) s += g_deg[i];
#pragma unroll
        for (int o = 16; o > 0; o >>= 1) s += __shfl_down_sync(0xffffffffu, s, o);
        if (lane == 0) swarp[warp] = s;
        __syncthreads();
        if (tid == 0) {
            int t = 0;
#pragma unroll
            for (int i = 0; i < 8; i++) t += swarp[i];
            g_part[bid] = t;
        }
    }
    gsync(++epoch, grid);

    // ===== Phase 3: off/cur (exclusive scan), zero deg =====
    {
        int pf = 0;
        for (int i = tid; i < bid; i += 256) pf += g_part[i];
#pragma unroll
        for (int o = 16; o > 0; o >>= 1) pf += __shfl_down_sync(0xffffffffu, pf, o);
        if (lane == 0) swarp[warp] = pf;
        __syncthreads();
        if (tid == 0) {
            int t = 0;
#pragma unroll
            for (int i = 0; i < 8; i++) t += swarp[i];
            sprefix = t;
        }
        __syncthreads();
        int prefix = sprefix;
        for (int seg = c0; seg < c1; seg += 256) {
            int idx = seg + tid;
            int v = (idx < c1) ? g_deg[idx] : 0;
            int inc = v;
#pragma unroll
            for (int o = 1; o < 32; o <<= 1) {
                int t = __shfl_up_sync(0xffffffffu, inc, o);
                if (lane >= o) inc += t;
            }
            __syncthreads();
            if (lane == 31) swarp[warp] = inc;
            __syncthreads();
            if (tid == 0) {
                int run = 0;
#pragma unroll
                for (int i = 0; i < 8; i++) { int t = swarp[i]; swarp[i] = run; run += t; }
                stotal = run;
            }
            __syncthreads();
            int ex = prefix + swarp[warp] + inc - v;
            if (idx < c1) { g_off[idx] = ex; g_cur[idx] = ex; g_deg[idx] = 0; }
            prefix += stotal;
            __syncthreads();
        }
        if (bid == 0 && tid == 0) g_off[N] = E;
    }
    gsync(++epoch, grid);

    // ===== Phase 4: CSR fill =====
    for (int e = bid * 256 + tid; e < E; e += grid * 256) {
        int src = ei[e];
        int dst = ei[E + e];
        int pos = atomicAdd(&g_cur[dst], 1);
        g_csr[pos] = src;
    }
    gsync(++epoch, grid);

    // ===== Phase 5: pull0 -> h =====
    for (int j = tid; j < 768; j += 256) sm[OFF_WE + j] = Wedge[j];
    __syncthreads();
    {
        int gw = bid * 8 + warp, stride = grid * 8;
        for (int node = gw; node < N; node += stride) {
            float2 a = pull_node(sm, node, lane, g_off, g_csr, g_t0, g_pre, g_EA);
            ((float2*)g_h)[node * 32 + lane] = make_float2(lrelu(a.x), lrelu(a.y));
        }
    }
    gsync(++epoch, grid);

    // ===== Phase 6: gemm1 (reads h; overwrites pre, writes t1) =====
    for (int j = tid; j < 2048; j += 256) {
        int k = j >> 5, c4 = j & 31;
        float4 wv = (c4 < 16) ? ((const float4*)(Wnbr + 4096))[k * 16 + c4]
                              : ((const float4*)(Wself + 4096))[k * 16 + (c4 - 16)];
        *(float4*)&sm[OFF_W + k * 128 + c4 * 4] = wv;
    }
    if (tid < 64) sm[OFF_B + tid] = bconv[64 + tid];
    __syncthreads();
    for (int tile = bid; tile < tiles; tile += grid)
        gemm_tile<false>(sm, tile * 64, N, nullptr, nullptr, g_h, g_t1, g_pre);
    gsync(++epoch, grid);

    // ===== Phase 7: pull1 + readout atomics =====
    for (int j = tid; j < 768; j += 256) sm[OFF_WE + j] = Wedge[768 + j];
    __syncthreads();
    {
        int gw = bid * 8 + warp, stride = grid * 8;
        float w0 = __ldg(&Wout[2 * lane]), w1 = __ldg(&Wout[2 * lane + 1]);
        float b0v = bout[0];
        for (int node = gw; node < N; node += stride) {
            float2 a = pull_node(sm, node, lane, g_off, g_csr, g_t1, g_pre, g_EA);
            float p2 = lrelu(a.x) * w0 + lrelu(a.y) * w1;
#pragma unroll
            for (int o = 16; o > 0; o >>= 1) p2 += __shfl_down_sync(0xffffffffu, p2, o);
            if (lane == 0) {
                int b = batch[node];
                atomicAdd(&g_sc[b], p2 + b0v);
                atomicAdd(&g_sc[NGRAPH + b], 1.0f);
            }
        }
    }
    gsync(++epoch, grid);

    // ===== Phase 8: finalize + restore invariants =====
    {
        int tot4 = N * 3;   // N*12/4 float4s
        float4* EA4 = (float4*)g_EA;
        for (int i = bid * 256 + tid; i < tot4; i += grid * 256)
            EA4[i] = make_float4(0.f, 0.f, 0.f, 0.f);
        if (bid == 0 && tid < G) {
            float sv = g_sc[tid], cv = g_sc[NGRAPH + tid];
            out[tid] = sv / fmaxf(cv, 1.0f);
            g_sc[tid] = 0.0f;
            g_sc[NGRAPH + tid] = 0.0f;
        }
    }

    // terminal arrive: last block resets the barrier counter for next replay
    __syncthreads();
    if (tid == 0) {
        __threadfence();
        unsigned int v = atomicAdd(&g_bar, 1u);
        if (v == (unsigned int)epoch * grid + grid - 1) atomicExch(&g_bar, 0u);
    }
}

// ---------------------------------------------------------------------------
extern "C" void kernel_launch(void* const* d_in, const int* in_sizes, int n_in,
                              void* d_out, int out_size) {
    const float* state     = (const float*)d_in[0];
    const float* action    = (const float*)d_in[1];
    const int*   edge_idx  = (const int*)d_in[2];
    const float* edge_attr = (const float*)d_in[3];
    const int*   batch     = (const int*)d_in[4];
    const float* W_in      = (const float*)d_in[5];
    const float* b_in      = (const float*)d_in[6];
    const float* W_self    = (const float*)d_in[7];
    const float* W_nbr     = (const float*)d_in[8];
    const float* W_edge    = (const float*)d_in[9];
    const float* b_conv    = (const float*)d_in[10];
    const float* W_out     = (const float*)d_in[11];
    const float* b_out     = (const float*)d_in[12];
    float* out = (float*)d_out;

    const int N = in_sizes[0] / 8;
    const int E = in_sizes[3] / 12;
    const int G = out_size;

    const int smemBytes = SMEM_FLOATS * 4;

    static int grid = 0;
    if (!grid) {
        cudaFuncSetAttribute(k_all, cudaFuncAttributeMaxDynamicSharedMemorySize, smemBytes);
        int perSM = 0;
        cudaOccupancyMaxActiveBlocksPerMultiprocessor(&perSM, k_all, 256, smemBytes);
        if (perSM < 1) perSM = 1;
        int dev = 0, sms = 0;
        cudaGetDevice(&dev);
        cudaDeviceGetAttribute(&sms, cudaDevAttrMultiProcessorCount, dev);
        grid = perSM * sms;
        if (grid > 2048) grid = 2048;   // g_part bound
    }

    k_all<<<grid, 256, smemBytes>>>(state, action, edge_idx, edge_attr, batch,
                                    W_in, b_in, W_self, W_nbr, W_edge, b_conv,
                                    W_out, b_out, out, N, E, G, grid);
}